// round 10
// baseline (speedup 1.0000x reference)
#include <cuda_runtime.h>
#include <cstdint>

// GatingFeatureExtractor: p[B, E=8, C=1000] fp32 -> feats[B, E*C + 3E + 5] fp32.
// Persistent-CTA, double-buffered pipeline (R3 phase bodies unchanged):
//   grid = 456 CTAs (152 SMs x 3), each loops rows bid, bid+456, ...
//   per row: prefetch NEXT row's 32KB via cp.async into the other buffer,
//   wait current buffer, then B (top2/argmax), C (plogp/cross/mix/var),
//   D (shift-corrected aligned copy), finalize. Row i+1's load overlaps
//   row i's compute -- removes the per-row stage-wait of the one-row design.

#define EPS_F 1e-8f

constexpr int E = 8;
constexpr int C = 1000;
constexpr int C4 = C / 4;                  // 250
constexpr int EC = E * C;                  // 8000
constexpr int OUTW = EC + 3 * E + 5;       // 8029
constexpr int NT = 256;
constexpr int NW = NT / 32;
constexpr int GRID = 456;                  // 152 SMs x 3 CTAs (smem-limited)

__device__ __forceinline__ void cp_async16(uint32_t saddr, const void* gptr) {
    asm volatile("cp.async.cg.shared.global [%0], [%1], 16;\n" ::"r"(saddr), "l"(gptr));
}

__global__ __launch_bounds__(NT, 3)
void gating_feats_kernel(const float* __restrict__ pin, float* __restrict__ out, int B)
{
    __shared__ __align__(16) float sp[2][EC + 4];  // +4 pad: Phase D overlap read
    __shared__ float sh_mx1[E], sh_mx2[E];
    __shared__ int   sh_ix1[E];
    __shared__ float sh_red[NW][11];               // plogp[8], cross, mixent, var

    const int tid  = threadIdx.x;
    const int wid  = tid >> 5;
    const int lane = tid & 31;

    // ---- stage helper: issue row's 32KB into buffer buf, one commit group ----
    auto stage = [&](int row, int buf) {
        const float* __restrict__ pr = pin + (size_t)row * EC;
        if (tid < C4) {
            uint32_t sbase = (uint32_t)__cvta_generic_to_shared(&sp[buf][0])
                           + 16u * (uint32_t)tid;
#pragma unroll
            for (int e = 0; e < E; e++)
                cp_async16(sbase + (uint32_t)(e * C * 4), pr + e * C + 4 * tid);
        }
        asm volatile("cp.async.commit_group;\n" ::: "memory");
    };

    int row0 = blockIdx.x;
    if (row0 < B) stage(row0, 0);

    int buf = 0;
    for (int row = row0; row < B; row += GRID, buf ^= 1) {
        const int nxt = row + GRID;
        if (nxt < B) stage(nxt, buf ^ 1);          // prefetch overlaps this row

        if (nxt < B) asm volatile("cp.async.wait_group 1;\n" ::: "memory");
        else         asm volatile("cp.async.wait_group 0;\n" ::: "memory");
        __syncthreads();                           // buf ready for all warps

        const float* __restrict__ spc = &sp[buf][0];
        float* __restrict__ orow = out + (size_t)row * OUTW;
        // (row*OUTW)%4 == row%4 since OUTW%4==1; dst float4 frame starts at h.
        const int h = (4 - (row & 3)) & 3;

        // -------- Phase B: per-expert top2/argmax (warp = expert), no MUFU ----
        {
            const float4* __restrict__ row4 =
                reinterpret_cast<const float4*>(spc + wid * C);
            float m1 = -1.f, m2 = -1.f;
            int i1 = 0;
#pragma unroll
            for (int k = 0; k < 8; k++) {
                int idx = lane + 32 * k;
                if (idx < C4) {
                    float4 v = row4[idx];
                    float vv[4] = {v.x, v.y, v.z, v.w};
#pragma unroll
                    for (int i = 0; i < 4; i++) {
                        float f = vv[i];
                        if (f > m1) { m2 = m1; m1 = f; i1 = 4 * idx + i; }
                        else        { m2 = fmaxf(m2, f); }
                    }
                }
            }
#pragma unroll
            for (int off = 16; off; off >>= 1) {
                float o1 = __shfl_xor_sync(0xffffffffu, m1, off);
                float o2 = __shfl_xor_sync(0xffffffffu, m2, off);
                int   oi = __shfl_xor_sync(0xffffffffu, i1, off);
                if (o1 > m1 || (o1 == m1 && oi < i1)) {
                    m2 = fmaxf(m1, o2); m1 = o1; i1 = oi;
                } else {
                    m2 = fmaxf(m2, o1);
                }
            }
            if (lane == 0) { sh_mx1[wid] = m1; sh_mx2[wid] = m2; sh_ix1[wid] = i1; }
        }

        // -------- Phase C: single-pass cross-expert stats + plogp ----
        {
            float plogp[E];
#pragma unroll
            for (int e = 0; e < E; e++) plogp[e] = 0.f;
            float s_cross = 0.f, s_mixent = 0.f, s_var = 0.f;

            if (tid < C4) {                         // thread owns classes 4t..4t+3
                float pre[4] = {0.f, 0.f, 0.f, 0.f};
                float ssq[4] = {0.f, 0.f, 0.f, 0.f};
#pragma unroll
                for (int e = 0; e < E; e++) {
                    float4 v = reinterpret_cast<const float4*>(spc + e * C)[tid];
                    float vv[4] = {v.x, v.y, v.z, v.w};
                    float pe = 0.f;
#pragma unroll
                    for (int i = 0; i < 4; i++) {
                        float f = vv[i];
                        float lg = __logf(f + EPS_F);
                        pe = fmaf(f, lg, pe);
                        s_cross = fmaf(lg, pre[i], s_cross);  // sum_{i<j} p_i*logp_j
                        pre[i] += f;
                        ssq[i] = fmaf(f, f, ssq[i]);
                    }
                    plogp[e] = pe;
                }
#pragma unroll
                for (int i = 0; i < 4; i++) {
                    float m = pre[i] * (1.0f / E);  // pre[] = full expert sum
                    s_mixent = fmaf(-m, __logf(m + EPS_F), s_mixent);
                    s_var = fmaf(ssq[i] - (float)E * m * m,
                                 1.0f / (float)(E - 1), s_var);
                }
            }
            float r[11];
#pragma unroll
            for (int e = 0; e < E; e++) r[e] = plogp[e];
            r[8] = s_cross; r[9] = s_mixent; r[10] = s_var;
#pragma unroll
            for (int off = 16; off; off >>= 1)
#pragma unroll
                for (int k = 0; k < 11; k++)
                    r[k] += __shfl_xor_sync(0xffffffffu, r[k], off);
            if (lane == 0)
#pragma unroll
                for (int k = 0; k < 11; k++) sh_red[wid][k] = r[k];
        }

        // -------- Phase D: copy smem -> out, shift-corrected aligned STG.128 ----
        {
            const float4* __restrict__ sp4 = reinterpret_cast<const float4*>(spc);
            if (h == 0) {
                float4* __restrict__ dst4 = reinterpret_cast<float4*>(orow);
                for (int j = tid; j < EC / 4; j += NT) dst4[j] = sp4[j];
            } else {
                const int nvec = (EC - h) >> 2;    // 1999
                float4* __restrict__ dst4 = reinterpret_cast<float4*>(orow + h);
                for (int j = tid; j < nvec; j += NT) {
                    float4 v = sp4[j];
                    float4 w = sp4[j + 1];          // padded overlap read
                    float4 o;
                    if (h == 1)      { o.x = v.y; o.y = v.z; o.z = v.w; o.w = w.x; }
                    else if (h == 2) { o.x = v.z; o.y = v.w; o.z = w.x; o.w = w.y; }
                    else             { o.x = v.w; o.y = w.x; o.z = w.y; o.w = w.z; }
                    dst4[j] = o;
                }
                if (tid < h)     orow[tid] = spc[tid];                     // head
                if (tid < 4 - h) orow[h + 4 * nvec + tid] = spc[h + 4 * nvec + tid];
            }
        }

        __syncthreads();                           // sh_red/sh_mx complete, buf free

        // -------- Finalize: 29 stat columns (thread 0; others proceed) ----
        if (tid == 0) {
            float acc[11];
#pragma unroll
            for (int k = 0; k < 11; k++) acc[k] = 0.f;
            for (int w = 0; w < NW; w++)
#pragma unroll
                for (int k = 0; k < 11; k++) acc[k] += sh_red[w][k];

            float sum_pl = 0.f, wsum = 0.f;
            int args[E];
#pragma unroll
            for (int e = 0; e < E; e++) {
                float pl = acc[e];
                orow[EC + e]         = -pl;                      // expert_entropy
                orow[EC + E + e]     = sh_mx1[e];                // expert_confidence
                orow[EC + 2 * E + e] = sh_mx1[e] - sh_mx2[e];    // expert_margin
                sum_pl += pl;
                wsum = fmaf(pl, (float)(E - 1 - e), wsum);
                args[e] = sh_ix1[e];
            }
            for (int i = 1; i < E; i++) {           // sort argmax idx, count unique
                int key = args[i]; int j = i - 1;
                while (j >= 0 && args[j] > key) { args[j + 1] = args[j]; j--; }
                args[j + 1] = key;
            }
            int nuniq = 1;
            for (int i = 1; i < E; i++) nuniq += (args[i] != args[i - 1]) ? 1 : 0;

            const int n_pairs = E * (E - 1) / 2;
            orow[EC + 3 * E + 0] = (float)(nuniq - 1) / (float)(E - 1);
            orow[EC + 3 * E + 1] = (wsum - acc[8]) / (float)n_pairs;
            orow[EC + 3 * E + 2] = acc[9];
            orow[EC + 3 * E + 3] = acc[10] / (float)C;
            orow[EC + 3 * E + 4] = acc[9] + sum_pl / (float)E;
        }
        // no extra barrier: next iteration's first barrier (post-wait
        // __syncthreads) orders finalize before sh_* are overwritten.
    }
}

extern "C" void kernel_launch(void* const* d_in, const int* in_sizes, int n_in,
                              void* d_out, int out_size)
{
    const float* p = (const float*)d_in[0];
    float* out = (float*)d_out;
    const int B = in_sizes[0] / EC;    // 8192 for this problem's shapes
    const int grid = (B < GRID) ? B : GRID;
    gating_feats_kernel<<<grid, NT>>>(p, out, B);
}

// round 11
// speedup vs baseline: 1.2346x; 1.2346x over previous
#include <cuda_runtime.h>
#include <cstdint>

// GatingFeatureExtractor: p[B, E=8, C=1000] fp32 -> feats[B, E*C + 3E + 5] fp32.
// Split-row design: 2 CTAs per row (128 threads, 16KB smem each), so ~12
// independent CTAs/SM pipeline load/compute/store via the HW scheduler.
//   k1 (grid 2B): CTA x -> (b = x>>1, half = x&1), classes [500*half, +500):
//     A: cp.async 16KB stage   B: warp w -> experts 2w,2w+1 top2/argmax partial
//     C: thread t<125 owns 4 classes: plogp[8], prefix-KL cross, mixture
//        entropy, variance partials    D: shifted aligned copy of 8 segments
//     partials -> __device__ scratch
//   k2 (1 thread/row): merge 2 partials, write the 29 stat columns.

#define EPS_F 1e-8f

constexpr int E = 8;
constexpr int C = 1000;
constexpr int EC = E * C;                  // 8000
constexpr int OUTW = EC + 3 * E + 5;       // 8029
constexpr int HALF = 500;                  // classes per CTA
constexpr int H4 = HALF / 4;               // 125 float4 per expert-segment
constexpr int NT = 128;
constexpr int NW = NT / 32;                // 4
constexpr int BMAX = 8192;

// partial scratch: index x = 2*b + half
__device__ float g_red[2 * BMAX][12];      // [0..7]=plogp, 8=cross, 9=mixent, 10=var
__device__ float g_m1[2 * BMAX][E];
__device__ float g_m2[2 * BMAX][E];
__device__ int   g_i1[2 * BMAX][E];

__device__ __forceinline__ void cp_async16(uint32_t saddr, const void* gptr) {
    asm volatile("cp.async.cg.shared.global [%0], [%1], 16;\n" ::"r"(saddr), "l"(gptr));
}

__global__ __launch_bounds__(NT)
void gating_feats_k1(const float* __restrict__ pin, float* __restrict__ out)
{
    __shared__ __align__(16) float sp[E * HALF];   // 16000 B
    __shared__ float sh_red[NW][11];

    const int x    = blockIdx.x;
    const int b    = x >> 1;
    const int half = x & 1;
    const int tid  = threadIdx.x;
    const int wid  = tid >> 5;
    const int lane = tid & 31;

    const float* __restrict__ pr = pin + (size_t)b * EC + half * HALF; // + e*C
    float* __restrict__ orow = out + (size_t)b * OUTW;
    // (b*OUTW)%4 == b%4 since OUTW%4==1; every segment start has same h.
    const int h = (4 - (b & 3)) & 3;

    // ---------------- Phase A: stage 8 x 2000B segments via cp.async ----------
    if (tid < H4) {
        uint32_t sbase = (uint32_t)__cvta_generic_to_shared(sp) + 16u * (uint32_t)tid;
#pragma unroll
        for (int e = 0; e < E; e++)
            cp_async16(sbase + (uint32_t)(e * HALF * 4), pr + e * C + 4 * tid);
    }
    asm volatile("cp.async.commit_group;\n" ::: "memory");
    asm volatile("cp.async.wait_group 0;\n" ::: "memory");
    __syncthreads();

    // -------- Phase B: warp w -> experts 2w, 2w+1: top2/argmax partial --------
#pragma unroll
    for (int s = 0; s < 2; s++) {
        const int e = 2 * wid + s;
        const float4* __restrict__ row4 = reinterpret_cast<const float4*>(sp + e * HALF);
        float m1 = -1.f, m2 = -1.f;
        int i1 = 0x7fffffff;
#pragma unroll
        for (int k = 0; k < 4; k++) {
            int idx = lane + 32 * k;
            if (idx < H4) {
                float4 v = row4[idx];
                float vv[4] = {v.x, v.y, v.z, v.w};
#pragma unroll
                for (int i = 0; i < 4; i++) {
                    float f = vv[i];
                    if (f > m1) { m2 = m1; m1 = f; i1 = half * HALF + 4 * idx + i; }
                    else        { m2 = fmaxf(m2, f); }
                }
            }
        }
#pragma unroll
        for (int off = 16; off; off >>= 1) {
            float o1 = __shfl_xor_sync(0xffffffffu, m1, off);
            float o2 = __shfl_xor_sync(0xffffffffu, m2, off);
            int   oi = __shfl_xor_sync(0xffffffffu, i1, off);
            if (o1 > m1 || (o1 == m1 && oi < i1)) {
                m2 = fmaxf(m1, o2); m1 = o1; i1 = oi;
            } else {
                m2 = fmaxf(m2, o1);
            }
        }
        if (lane == 0) { g_m1[x][e] = m1; g_m2[x][e] = m2; g_i1[x][e] = i1; }
    }

    // -------- Phase C: thread t<125 owns local classes 4t..4t+3 --------
    {
        float plogp[E];
#pragma unroll
        for (int e = 0; e < E; e++) plogp[e] = 0.f;
        float s_cross = 0.f, s_mixent = 0.f, s_var = 0.f;

        if (tid < H4) {
            float pre[4] = {0.f, 0.f, 0.f, 0.f};
            float ssq[4] = {0.f, 0.f, 0.f, 0.f};
#pragma unroll
            for (int e = 0; e < E; e++) {
                float4 v = reinterpret_cast<const float4*>(sp + e * HALF)[tid];
                float vv[4] = {v.x, v.y, v.z, v.w};
                float pe = 0.f;
#pragma unroll
                for (int i = 0; i < 4; i++) {
                    float f = vv[i];
                    float lg = __logf(f + EPS_F);
                    pe = fmaf(f, lg, pe);
                    s_cross = fmaf(lg, pre[i], s_cross);  // sum_{i<j} p_i * logp_j
                    pre[i] += f;
                    ssq[i] = fmaf(f, f, ssq[i]);
                }
                plogp[e] = pe;
            }
#pragma unroll
            for (int i = 0; i < 4; i++) {
                float m = pre[i] * (1.0f / E);      // full expert sum for this class
                s_mixent = fmaf(-m, __logf(m + EPS_F), s_mixent);
                s_var = fmaf(ssq[i] - (float)E * m * m, 1.0f / (float)(E - 1), s_var);
            }
        }
        float r[11];
#pragma unroll
        for (int e = 0; e < E; e++) r[e] = plogp[e];
        r[8] = s_cross; r[9] = s_mixent; r[10] = s_var;
#pragma unroll
        for (int off = 16; off; off >>= 1)
#pragma unroll
            for (int k = 0; k < 11; k++)
                r[k] += __shfl_xor_sync(0xffffffffu, r[k], off);
        if (lane == 0)
#pragma unroll
            for (int k = 0; k < 11; k++) sh_red[wid][k] = r[k];
    }
    __syncthreads();
    if (tid == 0) {
#pragma unroll
        for (int k = 0; k < 11; k++)
            g_red[x][k] = sh_red[0][k] + sh_red[1][k] + sh_red[2][k] + sh_red[3][k];
    }

    // -------- Phase D: copy 8 segments, shift-corrected aligned STG.128 --------
    {
#pragma unroll
        for (int e = 0; e < E; e++) {
            const float* __restrict__ seg = sp + e * HALF;
            const float4* __restrict__ seg4 = reinterpret_cast<const float4*>(seg);
            float* __restrict__ dseg = orow + e * C + half * HALF;   // b%4 offset
            if (h == 0) {
                if (tid < H4)
                    reinterpret_cast<float4*>(dseg)[tid] = seg4[tid];
            } else {
                // 500 = h + 4*124 + (4-h); all reads within this segment
                if (tid < h) dseg[tid] = seg[tid];
                if (tid < 124) {
                    float4 v = seg4[tid];
                    float4 w = seg4[tid + 1];
                    float4 o;
                    if (h == 1)      { o.x = v.y; o.y = v.z; o.z = v.w; o.w = w.x; }
                    else if (h == 2) { o.x = v.z; o.y = v.w; o.z = w.x; o.w = w.y; }
                    else             { o.x = v.w; o.y = w.x; o.z = w.y; o.w = w.z; }
                    *reinterpret_cast<float4*>(dseg + h + 4 * tid) = o;
                }
                if (tid < 4 - h) dseg[h + 496 + tid] = seg[h + 496 + tid];
            }
        }
    }
}

// ---- combine: 1 thread per row merges the two halves, writes 29 columns ----
__global__ void gating_feats_k2(float* __restrict__ out, int B)
{
    int b = blockIdx.x * blockDim.x + threadIdx.x;
    if (b >= B) return;
    float* __restrict__ orow = out + (size_t)b * OUTW;
    const int p0 = 2 * b, p1 = 2 * b + 1;

    float acc[11];
#pragma unroll
    for (int k = 0; k < 11; k++) acc[k] = g_red[p0][k] + g_red[p1][k];

    float sum_pl = 0.f, wsum = 0.f;
    int args[E];
#pragma unroll
    for (int e = 0; e < E; e++) {
        float m1 = g_m1[p0][e], m2 = g_m2[p0][e];
        int   i1 = g_i1[p0][e];
        float o1 = g_m1[p1][e], o2 = g_m2[p1][e];
        int   oi = g_i1[p1][e];
        if (o1 > m1 || (o1 == m1 && oi < i1)) {
            m2 = fmaxf(m1, o2); m1 = o1; i1 = oi;
        } else {
            m2 = fmaxf(m2, o1);
        }
        float pl = acc[e];
        orow[EC + e]         = -pl;                  // expert_entropy
        orow[EC + E + e]     = m1;                   // expert_confidence
        orow[EC + 2 * E + e] = m1 - m2;              // expert_margin
        sum_pl += pl;
        wsum = fmaf(pl, (float)(E - 1 - e), wsum);
        args[e] = i1;
    }

    // disagreement: sort 8 argmax indices, count unique
    for (int i = 1; i < E; i++) {
        int key = args[i]; int j = i - 1;
        while (j >= 0 && args[j] > key) { args[j + 1] = args[j]; j--; }
        args[j + 1] = key;
    }
    int nuniq = 1;
    for (int i = 1; i < E; i++) nuniq += (args[i] != args[i - 1]) ? 1 : 0;

    const int n_pairs = E * (E - 1) / 2;
    orow[EC + 3 * E + 0] = (float)(nuniq - 1) / (float)(E - 1);  // disagreement_ratio
    orow[EC + 3 * E + 1] = (wsum - acc[8]) / (float)n_pairs;     // mean_pairwise_kl
    orow[EC + 3 * E + 2] = acc[9];                               // mixture_entropy
    orow[EC + 3 * E + 3] = acc[10] / (float)C;                   // post_var
    orow[EC + 3 * E + 4] = acc[9] + sum_pl / (float)E;           // mutual_info
}

extern "C" void kernel_launch(void* const* d_in, const int* in_sizes, int n_in,
                              void* d_out, int out_size)
{
    const float* p = (const float*)d_in[0];
    float* out = (float*)d_out;
    const int B = in_sizes[0] / EC;    // 8192 for this problem's shapes
    gating_feats_k1<<<2 * B, NT>>>(p, out);
    gating_feats_k2<<<(B + 127) / 128, 128>>>(out, B);
}